// round 5
// baseline (speedup 1.0000x reference)
#include <cuda_runtime.h>
#include <cuda_bf16.h>

// Problem constants
#define BB   512    // batch
#define TT   256    // time steps
#define II   256    // input dim
#define HH   256    // hidden dim

// Tiling
#define NBLK 128    // 8 batch-tiles x 16 hidden-tiles (must all be co-resident: 128 <= 148 SMs)
#define BTIL 64     // batch rows per block
#define HTIL 16     // hidden units per block (x4 gates = 64 gate rows)
#define LD   68     // smem row stride (floats), padded

// Scratch (allocation-free rule: __device__ globals)
__device__ float        g_hs[(size_t)BB * TT * HH];   // h at every step  (128 MB)
__device__ float        g_cfin[(size_t)BB * HH];      // final cell state
__device__ unsigned int g_bar;                        // grid barrier counter

__global__ void init_kernel() { g_bar = 0u; }

__device__ __forceinline__ float sigf(float v) { return 1.0f / (1.0f + __expf(-v)); }

#define PACK2(D, LO, HI)  asm("mov.b64 %0,{%1,%2};" : "=l"(D) : "f"(LO), "f"(HI))
#define UNPACK2(LO, HI, S) asm("mov.b64 {%0,%1},%2;" : "=f"(LO), "=f"(HI) : "l"(S))
#define FMA2(ACC, AA, BV)  asm("fma.rn.f32x2 %0,%1,%2,%0;" : "+l"(ACC) : "l"(AA), "l"(BV))

// Persistent recurrent kernel.
// Grid: 128 blocks. blockIdx.x = hb*8 + bb ; bb in [0,8) batch tile, hb in [0,16) hidden tile.
// Each block: keeps W slice [64 gate rows x 512 K] in smem for all T steps,
// owns c for its (64 batch x 16 hidden) slice in registers, exchanges h via g_hs
// with a monotonic atomic grid barrier per step.
__global__ void __launch_bounds__(256, 1) lstm_rec(
    const float* __restrict__ x,        // [B,T,I]
    const int*   __restrict__ is_init,  // [B,T]
    const float* __restrict__ hx,       // [B,1,H]
    const float* __restrict__ cx,       // [B,1,H]
    const float* __restrict__ Wih,      // [4H,I]
    const float* __restrict__ Whh,      // [4H,H]
    const float* __restrict__ bih,      // [4H]
    const float* __restrict__ bhh)      // [4H]
{
    extern __shared__ float sm[];
    float* Ws   = sm;                 // [512][LD]  weight slice, W[k][r]
    float* As   = Ws + 512 * LD;      // [64][LD]   A chunk, A[kk][row]
    float* Gs   = As + 64 * LD;       // [64][LD]   gates, G[row][r]
    float* bias = Gs + 64 * LD;       // [64]
    float* rset = bias + 64;          // [64]

    const int tid = threadIdx.x;
    const int bb  = blockIdx.x & 7;
    const int hb  = blockIdx.x >> 3;
    const int b0  = bb * BTIL;
    const int h0  = hb * HTIL;

    // ---- one-time: load W slice (rows: r = g*16 + j -> global row g*256 + h0 + j) ----
    for (int idx = tid; idx < 64 * 512; idx += 256) {
        int r  = idx >> 9;          // 0..63
        int k  = idx & 511;         // 0..511 (coalesced)
        int gr = (r >> 4) * HH + h0 + (r & 15);
        float w = (k < 256) ? Wih[gr * II + k] : Whh[gr * HH + (k - 256)];
        Ws[k * LD + r] = w;
    }
    if (tid < 64) {
        int gr = (tid >> 4) * HH + h0 + (tid & 15);
        bias[tid] = bih[gr] + bhh[gr];
    }

    const int tx  = tid & 15, ty = tid >> 4;
    const int tx4 = tx * 4,  ty4 = ty * 4;
    const int rloc = tid >> 2;           // batch row (0..63) for loads & c-update
    const int kq   = (tid & 3) * 4;      // k/j sub-offset

    // ---- cell state registers for this thread's 4 elements: (b0+rloc, h0+kq+m) ----
    float c[4];
    {
        float4 cv = *reinterpret_cast<const float4*>(cx + (size_t)(b0 + rloc) * HH + h0 + kq);
        c[0] = cv.x; c[1] = cv.y; c[2] = cv.z; c[3] = cv.w;
    }

    for (int t = 0; t < TT; ++t) {
        if (tid < 64) rset[tid] = 1.0f - (float)is_init[(size_t)(b0 + tid) * TT + t];

        unsigned long long acc[4][2];
        #pragma unroll
        for (int i = 0; i < 4; ++i) { acc[i][0] = 0ull; acc[i][1] = 0ull; }

        // ---- GEMM: gates[64 x 64] = A[64 x 512] * Wslice^T, K chunks of 64 ----
        for (int ch = 0; ch < 8; ++ch) {
            __syncthreads();
            if (ch < 4) {  // x part, k in [0,256)
                const float* src = x + ((size_t)(b0 + rloc) * TT + t) * II + ch * 64;
                #pragma unroll
                for (int q = 0; q < 4; ++q) {
                    int kk = kq + q * 16;
                    float4 v = *reinterpret_cast<const float4*>(src + kk);
                    As[(kk + 0) * LD + rloc] = v.x;
                    As[(kk + 1) * LD + rloc] = v.y;
                    As[(kk + 2) * LD + rloc] = v.z;
                    As[(kk + 3) * LD + rloc] = v.w;
                }
            } else {       // h part, k in [256,512): h_prev * reset
                float rs = rset[rloc];
                const float* hsrc = (t == 0)
                    ? (hx + (size_t)(b0 + rloc) * HH)
                    : (g_hs + ((size_t)(b0 + rloc) * TT + (t - 1)) * HH);
                int khb = (ch - 4) * 64;
                #pragma unroll
                for (int q = 0; q < 4; ++q) {
                    int kk = kq + q * 16;
                    float4 v = *reinterpret_cast<const float4*>(hsrc + khb + kk);
                    As[(kk + 0) * LD + rloc] = v.x * rs;
                    As[(kk + 1) * LD + rloc] = v.y * rs;
                    As[(kk + 2) * LD + rloc] = v.z * rs;
                    As[(kk + 3) * LD + rloc] = v.w * rs;
                }
            }
            __syncthreads();

            const float* Wc = Ws + ch * 64 * LD;
            #pragma unroll 16
            for (int kk = 0; kk < 64; ++kk) {
                float4 av = *reinterpret_cast<const float4*>(As + kk * LD + ty4);
                float4 bv = *reinterpret_cast<const float4*>(Wc + kk * LD + tx4);
                unsigned long long b01, b23, aa;
                PACK2(b01, bv.x, bv.y);
                PACK2(b23, bv.z, bv.w);
                PACK2(aa, av.x, av.x); FMA2(acc[0][0], aa, b01); FMA2(acc[0][1], aa, b23);
                PACK2(aa, av.y, av.y); FMA2(acc[1][0], aa, b01); FMA2(acc[1][1], aa, b23);
                PACK2(aa, av.z, av.z); FMA2(acc[2][0], aa, b01); FMA2(acc[2][1], aa, b23);
                PACK2(aa, av.w, av.w); FMA2(acc[3][0], aa, b01); FMA2(acc[3][1], aa, b23);
            }
        }

        // ---- scatter gates to smem so each thread can gather i/f/g/o ----
        #pragma unroll
        for (int i = 0; i < 4; ++i) {
            float g0, g1, g2, g3;
            UNPACK2(g0, g1, acc[i][0]);
            UNPACK2(g2, g3, acc[i][1]);
            *reinterpret_cast<float4*>(Gs + (ty4 + i) * LD + tx4) = make_float4(g0, g1, g2, g3);
        }
        __syncthreads();

        // ---- elementwise: c/h update for this thread's 4 (b,h) elements ----
        {
            float rs = rset[rloc];
            float hv[4];
            #pragma unroll
            for (int m = 0; m < 4; ++m) {
                int j = kq + m;
                float gi = sigf (Gs[rloc * LD + j]      + bias[j]);
                float gf = sigf (Gs[rloc * LD + 16 + j] + bias[16 + j]);
                float gg = tanhf(Gs[rloc * LD + 32 + j] + bias[32 + j]);
                float go = sigf (Gs[rloc * LD + 48 + j] + bias[48 + j]);
                float cc = c[m] * rs;
                cc = gf * cc + gi * gg;
                c[m] = cc;
                hv[m] = go * tanhf(cc);
            }
            *reinterpret_cast<float4*>(
                g_hs + ((size_t)(b0 + rloc) * TT + t) * HH + h0 + kq)
                = make_float4(hv[0], hv[1], hv[2], hv[3]);
        }

        // ---- grid barrier (monotonic counter; g_bar zeroed by init_kernel) ----
        __threadfence();            // release h writes (all threads)
        __syncthreads();
        if (tid == 0) {
            atomicAdd(&g_bar, 1u);
            unsigned int target = (unsigned int)(t + 1) * (unsigned int)NBLK;
            while (*((volatile unsigned int*)&g_bar) < target) { }
        }
        __syncthreads();
        __threadfence();            // acquire other blocks' h writes
    }

    // final cell state
    *reinterpret_cast<float4*>(g_cfin + (size_t)(b0 + rloc) * HH + h0 + kq)
        = make_float4(c[0], c[1], c[2], c[3]);
}

// Epilogue: LayerNorm(h) + x skip, plus broadcast hT and cT.
// One warp per (b,t) row of 256; 8 warps/block; grid = B*T/8.
__global__ void __launch_bounds__(256) lstm_epi(
    const float* __restrict__ x,
    const float* __restrict__ lnw,
    const float* __restrict__ lnb,
    float* __restrict__ out)
{
    const int warp = threadIdx.x >> 5;
    const int lane = threadIdx.x & 31;
    const size_t row = (size_t)blockIdx.x * 8 + warp;   // 0..B*T-1
    const int b = (int)(row >> 8);                       // T = 256

    const float* hrow = g_hs + row * HH;
    float4 a  = *reinterpret_cast<const float4*>(hrow + lane * 4);
    float4 bq = *reinterpret_cast<const float4*>(hrow + 128 + lane * 4);

    float s  = a.x + a.y + a.z + a.w + bq.x + bq.y + bq.z + bq.w;
    float ss = a.x*a.x + a.y*a.y + a.z*a.z + a.w*a.w
             + bq.x*bq.x + bq.y*bq.y + bq.z*bq.z + bq.w*bq.w;
    #pragma unroll
    for (int o = 16; o > 0; o >>= 1) {
        s  += __shfl_xor_sync(0xffffffffu, s,  o);
        ss += __shfl_xor_sync(0xffffffffu, ss, o);
    }
    float mu  = s * (1.0f / 256.0f);
    float var = ss * (1.0f / 256.0f) - mu * mu;
    float inv = rsqrtf(var + 1e-5f);

    const size_t N1 = (size_t)BB * TT * HH;
    const float* hT = g_hs + ((size_t)b * TT + (TT - 1)) * HH;
    const float* cT = g_cfin + (size_t)b * HH;

    #pragma unroll
    for (int half = 0; half < 2; ++half) {
        int i0 = half * 128 + lane * 4;
        float4 hv = half ? bq : a;
        float4 xv = *reinterpret_cast<const float4*>(x   + row * II + i0);
        float4 wv = *reinterpret_cast<const float4*>(lnw + i0);
        float4 bv = *reinterpret_cast<const float4*>(lnb + i0);
        float4 o1;
        o1.x = xv.x + (hv.x - mu) * inv * wv.x + bv.x;
        o1.y = xv.y + (hv.y - mu) * inv * wv.y + bv.y;
        o1.z = xv.z + (hv.z - mu) * inv * wv.z + bv.z;
        o1.w = xv.w + (hv.w - mu) * inv * wv.w + bv.w;
        *reinterpret_cast<float4*>(out + row * HH + i0) = o1;

        *reinterpret_cast<float4*>(out + N1 + row * HH + i0)
            = *reinterpret_cast<const float4*>(hT + i0);
        *reinterpret_cast<float4*>(out + 2 * N1 + row * HH + i0)
            = *reinterpret_cast<const float4*>(cT + i0);
    }
}

extern "C" void kernel_launch(void* const* d_in, const int* in_sizes, int n_in,
                              void* d_out, int out_size) {
    const float* x       = (const float*)d_in[0];
    const int*   is_init = (const int*)  d_in[1];
    const float* hx      = (const float*)d_in[2];
    const float* cx      = (const float*)d_in[3];
    const float* Wih     = (const float*)d_in[4];
    const float* Whh     = (const float*)d_in[5];
    const float* bih     = (const float*)d_in[6];
    const float* bhh     = (const float*)d_in[7];
    const float* lnw     = (const float*)d_in[8];
    const float* lnb     = (const float*)d_in[9];
    float* out = (float*)d_out;

    const size_t smem = (size_t)(512 * LD + 64 * LD + 64 * LD + 128) * sizeof(float);
    cudaFuncSetAttribute(lstm_rec, cudaFuncAttributeMaxDynamicSharedMemorySize, (int)smem);

    init_kernel<<<1, 1>>>();
    lstm_rec<<<NBLK, 256, smem>>>(x, is_init, hx, cx, Wih, Whh, bih, bhh);
    lstm_epi<<<(BB * TT) / 8, 256>>>(x, lnw, lnb, out);
}